// round 3
// baseline (speedup 1.0000x reference)
#include <cuda_runtime.h>
#include <cuda_fp16.h>
#include <math.h>
#include <stdint.h>

#define N_NODES 8192
#define IN_F    512
#define OUT_F   64

// Scratch (device globals; no allocation allowed)
__device__ float  d_h[N_NODES * OUT_F];        // h = X @ W
__device__ float  d_r[N_NODES];                // r_j = h[j] . a_right
__device__ float  d_pmax[32];                  // per-block maxima of r
__device__ __half d_HpT[80 * N_NODES];         // transposed [w*h | w | pad], n-major

// ---------------------------------------------------------------------------
// common helpers
// ---------------------------------------------------------------------------
__device__ __forceinline__ void mma16816(float* c,
    uint32_t a0, uint32_t a1, uint32_t a2, uint32_t a3,
    uint32_t b0, uint32_t b1) {
    asm volatile(
        "mma.sync.aligned.m16n8k16.row.col.f32.f16.f16.f32 "
        "{%0,%1,%2,%3},{%4,%5,%6,%7},{%8,%9},{%0,%1,%2,%3};\n"
        : "+f"(c[0]), "+f"(c[1]), "+f"(c[2]), "+f"(c[3])
        : "r"(a0), "r"(a1), "r"(a2), "r"(a3), "r"(b0), "r"(b1));
}

__device__ __forceinline__ void ldsm_x4(uint32_t& r0, uint32_t& r1,
                                        uint32_t& r2, uint32_t& r3, uint32_t addr) {
    asm volatile("ldmatrix.sync.aligned.m8n8.x4.shared.b16 {%0,%1,%2,%3}, [%4];\n"
        : "=r"(r0), "=r"(r1), "=r"(r2), "=r"(r3) : "r"(addr));
}
__device__ __forceinline__ void ldsm_x2(uint32_t& r0, uint32_t& r1, uint32_t addr) {
    asm volatile("ldmatrix.sync.aligned.m8n8.x2.shared.b16 {%0,%1}, [%2];\n"
        : "=r"(r0), "=r"(r1) : "r"(addr));
}

__device__ __forceinline__ void cpa16(void* dst, const void* src) {
    uint32_t d = (uint32_t)__cvta_generic_to_shared(dst);
    asm volatile("cp.async.cg.shared.global [%0], [%1], 16;\n" :: "r"(d), "l"(src));
}
#define CP_COMMIT() asm volatile("cp.async.commit_group;\n" ::: "memory")
#define CP_WAIT(n)  asm volatile("cp.async.wait_group %0;\n" :: "n"(n) : "memory")

__device__ __forceinline__ float elu1(float x) {
    return x > 0.f ? x : expm1f(x);
}

// ---------------------------------------------------------------------------
// K1: h = X @ W  via fp16 mma (8192x512 @ 512x64), fp32 accumulate.
// ---------------------------------------------------------------------------
#define K1_XS   (3 * 64 * 68)                       // floats
#define K1_SMEM (K1_XS * 4 + 64 * 520 * 2)          // 118784 B

__global__ void __launch_bounds__(128)
k1_mma(const float* __restrict__ X, const float* __restrict__ W) {
    extern __shared__ char sm1[];
    float*  Xs = (float*)sm1;                        // [3][64][68]
    __half* Wt = (__half*)(sm1 + K1_XS * 4);         // [64 n][520 k]

    const int tid  = threadIdx.x;
    const int warp = tid >> 5;
    const int lane = tid & 31;
    const int g    = lane >> 2;
    const int t    = lane & 3;
    const int row0 = blockIdx.x * 64;

    for (int i = 0; i < 64; ++i) {
        int idx = i * 128 + tid;
        int k = idx >> 4, n = (idx & 15) * 4;
        float4 f = ((const float4*)W)[idx];
        Wt[(n + 0) * 520 + k] = __float2half(f.x);
        Wt[(n + 1) * 520 + k] = __float2half(f.y);
        Wt[(n + 2) * 520 + k] = __float2half(f.z);
        Wt[(n + 3) * 520 + k] = __float2half(f.w);
    }

    auto issueX = [&](int c) {
        int kc = c * 64;
        float* Xd = Xs + (c % 3) * 64 * 68;
#pragma unroll
        for (int q = 0; q < 8; ++q) {
            int idx = q * 128 + tid;
            int rr = idx >> 4, c4 = idx & 15;
            cpa16(Xd + rr * 68 + c4 * 4,
                  X + (size_t)(row0 + rr) * IN_F + kc + c4 * 4);
        }
    };
    issueX(0); CP_COMMIT();
    issueX(1); CP_COMMIT();

    float acc[8][4];
#pragma unroll
    for (int n = 0; n < 8; ++n)
#pragma unroll
        for (int i = 0; i < 4; ++i) acc[n][i] = 0.f;

    const int rb = warp * 16;
    for (int c = 0; c < 8; ++c) {
        CP_WAIT(1);
        __syncthreads();
        if (c + 2 < 8) issueX(c + 2);
        CP_COMMIT();

        const float* Xst = Xs + (c % 3) * 64 * 68;
#pragma unroll
        for (int ks = 0; ks < 4; ++ks) {
            int kk = ks * 16 + 2 * t;
            float2 f;
            __half2 h2;
            f = *(const float2*)&Xst[(rb + g) * 68 + kk];
            h2 = __float22half2_rn(f); uint32_t a0 = *(uint32_t*)&h2;
            f = *(const float2*)&Xst[(rb + g + 8) * 68 + kk];
            h2 = __float22half2_rn(f); uint32_t a1 = *(uint32_t*)&h2;
            f = *(const float2*)&Xst[(rb + g) * 68 + kk + 8];
            h2 = __float22half2_rn(f); uint32_t a2 = *(uint32_t*)&h2;
            f = *(const float2*)&Xst[(rb + g + 8) * 68 + kk + 8];
            h2 = __float22half2_rn(f); uint32_t a3 = *(uint32_t*)&h2;

            int kg = c * 64 + kk;
#pragma unroll
            for (int nt = 0; nt < 8; ++nt) {
                int n = nt * 8 + g;
                uint32_t b0 = *(const uint32_t*)&Wt[n * 520 + kg];
                uint32_t b1 = *(const uint32_t*)&Wt[n * 520 + kg + 8];
                mma16816(acc[nt], a0, a1, a2, a3, b0, b1);
            }
        }
    }

    const int rlo = row0 + rb + g;
    const int rhi = rlo + 8;
#pragma unroll
    for (int nt = 0; nt < 8; ++nt) {
        int c0 = nt * 8 + 2 * t;
        *(float2*)&d_h[(size_t)rlo * OUT_F + c0] = make_float2(acc[nt][0], acc[nt][1]);
        *(float2*)&d_h[(size_t)rhi * OUT_F + c0] = make_float2(acc[nt][2], acc[nt][3]);
    }
}

// ---------------------------------------------------------------------------
// K2: r_j = h[j] . a_right ; per-block max -> d_pmax
// ---------------------------------------------------------------------------
__global__ void k2_scores(const float* __restrict__ avec) {
    __shared__ float ar[64];
    __shared__ float red[256];
    const int tid = threadIdx.x;
    const int j   = blockIdx.x * 256 + tid;
    if (tid < 64) ar[tid] = avec[OUT_F + tid];   // a_right
    __syncthreads();

    const float4* h4 = (const float4*)&d_h[(size_t)j * OUT_F];
    float s = 0.f;
#pragma unroll
    for (int q = 0; q < 16; ++q) {
        float4 v = h4[q];
        s += v.x * ar[q * 4 + 0] + v.y * ar[q * 4 + 1]
           + v.z * ar[q * 4 + 2] + v.w * ar[q * 4 + 3];
    }
    d_r[j] = s;

    red[tid] = s;
    __syncthreads();
    for (int st = 128; st > 0; st >>= 1) {
        if (tid < st) red[tid] = fmaxf(red[tid], red[tid + st]);
        __syncthreads();
    }
    if (tid == 0) d_pmax[blockIdx.x] = red[0];
}

// ---------------------------------------------------------------------------
// K3: w_j = exp(r_j - m); build HpT[c][j] (fp16, n-major, padded to 80)
// ---------------------------------------------------------------------------
__global__ void k3_build() {
    __shared__ float hs[128][65];
    __shared__ float smax;
    const int tid = threadIdx.x;
    const int j0  = blockIdx.x * 128;
    if (tid == 0) {
        float m = d_pmax[0];
#pragma unroll
        for (int i = 1; i < 32; ++i) m = fmaxf(m, d_pmax[i]);
        smax = m;
    }
#pragma unroll
    for (int it = 0; it < 64; ++it) {
        int idx = it * 128 + tid;
        int rr = idx >> 6, cc = idx & 63;
        hs[rr][cc] = d_h[(size_t)(j0 + rr) * OUT_F + cc];
    }
    __syncthreads();
    float w = expf(d_r[j0 + tid] - smax);
#pragma unroll
    for (int c = 0; c < 80; ++c) {
        float v = (c < 64) ? w * hs[tid][c] : ((c == 64) ? w : 0.f);
        d_HpT[(size_t)c * N_NODES + j0 + tid] = __float2half(v);
    }
}

// ---------------------------------------------------------------------------
// K4: C[8192 x 80] = A(0/1 int32) @ Hp(fp16), then out = elu(num/den)
// 128 CTAs x 256 threads (8 warps = rg 0..3 x ng 0..1).
// A: LDG int4 (prefetch depth 2) -> fp16 convert -> STS, 2 smem stages.
// B: 4-stage cp.async. Fragments via ldmatrix, conflict-free (stride 72).
// ---------------------------------------------------------------------------
#define A_STRIDE 72
#define A_STAGE  (64 * A_STRIDE)             // halves
#define B_STAGE  (80 * A_STRIDE)             // halves
#define K4_SMEM  (2 * A_STAGE * 2 + 4 * B_STAGE * 2 + 256)

__global__ void __launch_bounds__(256)
k4_main(const int* __restrict__ adj, float* __restrict__ out) {
    extern __shared__ char sm4[];
    __half* Asm   = (__half*)sm4;                               // [2][64][72]
    __half* Bsm   = (__half*)(sm4 + 2 * A_STAGE * 2);           // [4][80][72]
    float*  den_s = (float*)(sm4 + 2 * A_STAGE * 2 + 4 * B_STAGE * 2);

    const int tid  = threadIdx.x;
    const int warp = tid >> 5;
    const int lane = tid & 31;
    const int t    = lane & 3;
    const int rg   = warp >> 1;
    const int ng   = warp & 1;
    const int row0 = blockIdx.x * 64;

    const uint32_t A0 = (uint32_t)__cvta_generic_to_shared(Asm);
    const uint32_t B0 = (uint32_t)__cvta_generic_to_shared(Bsm);

    // ldmatrix lane addressing
    const int quad = lane >> 3;            // 0..3
    const int qr   = lane & 7;
    const int rb   = rg * 16;
    // A: matrix m = quad: row = rb + (quad&1)*8 + qr, col8 = (quad>>1)*8
    const uint32_t aoff = (uint32_t)((rb + (quad & 1) * 8 + qr) * (A_STRIDE * 2)
                                     + (quad >> 1) * 16);
    // B pair p: tiles (ng*5+2p, +1): row = n0 + (quad>>1)*8 + qr, col8 = (quad&1)*8
    uint32_t boff[2];
#pragma unroll
    for (int p = 0; p < 2; ++p) {
        int n0 = (ng * 5 + 2 * p) * 8;
        boff[p] = (uint32_t)((n0 + (quad >> 1) * 8 + qr) * (A_STRIDE * 2)
                             + (quad & 1) * 16);
    }
    // B tile 4 (x2): lanes 0..15: row = n0 + qr, col8 = ((lane>>3)&1)*8
    const uint32_t boff4 = (uint32_t)(((ng * 5 + 4) * 8 + qr) * (A_STRIDE * 2)
                                      + (quad & 1) * 16);

    // --- A register prefetch (depth 2) ---
    const int4* adj4 = (const int4*)adj;
    int4 aPre[2][4];
    auto ldgA = [&](int c, int buf) {
#pragma unroll
        for (int q = 0; q < 4; ++q) {
            int idx = q * 256 + tid;
            int rr = idx >> 4, c4 = idx & 15;
            aPre[buf][q] = __ldg(&adj4[(size_t)(row0 + rr) * 2048 + c * 16 + c4]);
        }
    };
    auto storeA = [&](int st, int buf) {
        __half* Ad = Asm + st * A_STAGE;
#pragma unroll
        for (int q = 0; q < 4; ++q) {
            int idx = q * 256 + tid;
            int rr = idx >> 4, c4 = idx & 15;
            int4 v = aPre[buf][q];
            uint32_t h01 = (v.x ? 0x3C00u : 0u) | (v.y ? 0x3C000000u : 0u);
            uint32_t h23 = (v.z ? 0x3C00u : 0u) | (v.w ? 0x3C000000u : 0u);
            *(uint2*)&Ad[rr * A_STRIDE + c4 * 4] = make_uint2(h01, h23);
        }
    };
    auto issueB = [&](int c) {
        __half* Bd = Bsm + (c & 3) * B_STAGE;
        int kc = c * 64;
#pragma unroll
        for (int q = 0; q < 3; ++q) {
            int idx = q * 256 + tid;
            if (idx < 640) {
                int rr = idx >> 3, s = idx & 7;
                cpa16(Bd + rr * A_STRIDE + s * 8,
                      d_HpT + (size_t)rr * N_NODES + kc + s * 8);
            }
        }
    };

    ldgA(0, 0);
    ldgA(1, 1);
    issueB(0); CP_COMMIT();
    issueB(1); CP_COMMIT();
    issueB(2); CP_COMMIT();

    float acc[5][4];
#pragma unroll
    for (int n = 0; n < 5; ++n)
#pragma unroll
        for (int i = 0; i < 4; ++i) acc[n][i] = 0.f;

    for (int c = 0; c < 128; ++c) {
        const int ab = c & 1;
        storeA(ab, ab);                       // STS fp16 A for this chunk
        if (c + 2 < 128) ldgA(c + 2, ab);     // refill the freed register buffer
        CP_WAIT(2);                           // B chunk c landed
        __syncthreads();                      // A visible + prev mma drained
        if (c + 3 < 128) { issueB(c + 3); CP_COMMIT(); }

        const uint32_t Ab = A0 + ab * (A_STAGE * 2) + aoff;
        const uint32_t Bb = B0 + (c & 3) * (B_STAGE * 2);

#pragma unroll
        for (int ks = 0; ks < 4; ++ks) {
            uint32_t a0, a1, a2, a3;
            ldsm_x4(a0, a1, a2, a3, Ab + ks * 32);
            uint32_t b[10];
            ldsm_x4(b[0], b[1], b[2], b[3], Bb + boff[0] + ks * 32);
            ldsm_x4(b[4], b[5], b[6], b[7], Bb + boff[1] + ks * 32);
            ldsm_x2(b[8], b[9], Bb + boff4 + ks * 32);
#pragma unroll
            for (int nt = 0; nt < 5; ++nt)
                mma16816(acc[nt], a0, a1, a2, a3, b[2 * nt], b[2 * nt + 1]);
        }
    }

    // epilogue: den is column 64 = global n-tile 8 = (ng=1, nt=3), t==0
    const int g   = lane >> 2;
    const int r0l = rb + g;
    __syncthreads();
    if (ng == 1 && t == 0) {
        den_s[r0l]     = acc[3][0];
        den_s[r0l + 8] = acc[3][2];
    }
    __syncthreads();
    float inv_lo = 1.f / den_s[r0l];
    float inv_hi = 1.f / den_s[r0l + 8];

    const int rlo = row0 + r0l;
    const int rhi = rlo + 8;
#pragma unroll
    for (int nt = 0; nt < 5; ++nt) {
        int gt = ng * 5 + nt;
        if (gt >= 8) break;                 // tiles 8,9 are den/padding
        int c0 = gt * 8 + 2 * t;
        float2 vlo = make_float2(elu1(acc[nt][0] * inv_lo), elu1(acc[nt][1] * inv_lo));
        float2 vhi = make_float2(elu1(acc[nt][2] * inv_hi), elu1(acc[nt][3] * inv_hi));
        *(float2*)&out[(size_t)rlo * OUT_F + c0] = vlo;
        *(float2*)&out[(size_t)rhi * OUT_F + c0] = vhi;
    }
}

// ---------------------------------------------------------------------------
extern "C" void kernel_launch(void* const* d_in, const int* in_sizes, int n_in,
                              void* d_out, int out_size) {
    const float* X    = (const float*)d_in[0];   // node_features 8192x512
    const int*   adj  = (const int*)  d_in[1];   // adjacency 8192x8192
    const float* W    = (const float*)d_in[2];   // weight 512x64
    const float* avec = (const float*)d_in[3];   // attention vector 128x1
    float* out = (float*)d_out;                  // 8192x64

    cudaFuncSetAttribute(k1_mma, cudaFuncAttributeMaxDynamicSharedMemorySize, K1_SMEM);
    cudaFuncSetAttribute(k4_main, cudaFuncAttributeMaxDynamicSharedMemorySize, K4_SMEM);

    k1_mma<<<128, 128, K1_SMEM>>>(X, W);
    k2_scores<<<32, 256>>>(avec);
    k3_build<<<64, 128>>>();
    k4_main<<<128, 256, K4_SMEM>>>(adj, out);
}

// round 4
// speedup vs baseline: 2.2995x; 2.2995x over previous
#include <cuda_runtime.h>
#include <cuda_fp16.h>
#include <math.h>
#include <stdint.h>

#define N_NODES 8192
#define IN_F    512
#define OUT_F   64

// Scratch (device globals; no allocation allowed)
__device__ float  d_h[N_NODES * OUT_F];        // h = X @ W
__device__ float  d_r[N_NODES];                // r_j = h[j] . a_right
__device__ float  d_pmax[32];                  // per-block maxima of r
__device__ __half d_HpT[80 * N_NODES];         // transposed [w*h | w | pad], n-major

// ---------------------------------------------------------------------------
// common helpers
// ---------------------------------------------------------------------------
__device__ __forceinline__ void mma16816(float* c,
    uint32_t a0, uint32_t a1, uint32_t a2, uint32_t a3,
    uint32_t b0, uint32_t b1) {
    asm volatile(
        "mma.sync.aligned.m16n8k16.row.col.f32.f16.f16.f32 "
        "{%0,%1,%2,%3},{%4,%5,%6,%7},{%8,%9},{%0,%1,%2,%3};\n"
        : "+f"(c[0]), "+f"(c[1]), "+f"(c[2]), "+f"(c[3])
        : "r"(a0), "r"(a1), "r"(a2), "r"(a3), "r"(b0), "r"(b1));
}

__device__ __forceinline__ void ldsm_x4(uint32_t& r0, uint32_t& r1,
                                        uint32_t& r2, uint32_t& r3, uint32_t addr) {
    asm volatile("ldmatrix.sync.aligned.m8n8.x4.shared.b16 {%0,%1,%2,%3}, [%4];\n"
        : "=r"(r0), "=r"(r1), "=r"(r2), "=r"(r3) : "r"(addr));
}
__device__ __forceinline__ void ldsm_x2(uint32_t& r0, uint32_t& r1, uint32_t addr) {
    asm volatile("ldmatrix.sync.aligned.m8n8.x2.shared.b16 {%0,%1}, [%2];\n"
        : "=r"(r0), "=r"(r1) : "r"(addr));
}

__device__ __forceinline__ void cpa16(void* dst, const void* src) {
    uint32_t d = (uint32_t)__cvta_generic_to_shared(dst);
    asm volatile("cp.async.cg.shared.global [%0], [%1], 16;\n" :: "r"(d), "l"(src));
}
#define CP_COMMIT() asm volatile("cp.async.commit_group;\n" ::: "memory")
#define CP_WAIT(n)  asm volatile("cp.async.wait_group %0;\n" :: "n"(n) : "memory")

__device__ __forceinline__ float elu1(float x) {
    return x > 0.f ? x : expm1f(x);
}

// ---------------------------------------------------------------------------
// K1: h = X @ W  via fp16 mma (8192x512 @ 512x64), fp32 accumulate.
// ---------------------------------------------------------------------------
#define K1_XS   (3 * 64 * 68)                       // floats
#define K1_SMEM (K1_XS * 4 + 64 * 520 * 2)          // 118784 B

__global__ void __launch_bounds__(128)
k1_mma(const float* __restrict__ X, const float* __restrict__ W) {
    extern __shared__ char sm1[];
    float*  Xs = (float*)sm1;                        // [3][64][68]
    __half* Wt = (__half*)(sm1 + K1_XS * 4);         // [64 n][520 k]

    const int tid  = threadIdx.x;
    const int warp = tid >> 5;
    const int lane = tid & 31;
    const int g    = lane >> 2;
    const int t    = lane & 3;
    const int row0 = blockIdx.x * 64;

    for (int i = 0; i < 64; ++i) {
        int idx = i * 128 + tid;
        int k = idx >> 4, n = (idx & 15) * 4;
        float4 f = ((const float4*)W)[idx];
        Wt[(n + 0) * 520 + k] = __float2half(f.x);
        Wt[(n + 1) * 520 + k] = __float2half(f.y);
        Wt[(n + 2) * 520 + k] = __float2half(f.z);
        Wt[(n + 3) * 520 + k] = __float2half(f.w);
    }

    auto issueX = [&](int c) {
        int kc = c * 64;
        float* Xd = Xs + (c % 3) * 64 * 68;
#pragma unroll
        for (int q = 0; q < 8; ++q) {
            int idx = q * 128 + tid;
            int rr = idx >> 4, c4 = idx & 15;
            cpa16(Xd + rr * 68 + c4 * 4,
                  X + (size_t)(row0 + rr) * IN_F + kc + c4 * 4);
        }
    };
    issueX(0); CP_COMMIT();
    issueX(1); CP_COMMIT();

    float acc[8][4];
#pragma unroll
    for (int n = 0; n < 8; ++n)
#pragma unroll
        for (int i = 0; i < 4; ++i) acc[n][i] = 0.f;

    const int rb = warp * 16;
    for (int c = 0; c < 8; ++c) {
        CP_WAIT(1);
        __syncthreads();
        if (c + 2 < 8) issueX(c + 2);
        CP_COMMIT();

        const float* Xst = Xs + (c % 3) * 64 * 68;
#pragma unroll
        for (int ks = 0; ks < 4; ++ks) {
            int kk = ks * 16 + 2 * t;
            float2 f;
            __half2 h2;
            f = *(const float2*)&Xst[(rb + g) * 68 + kk];
            h2 = __float22half2_rn(f); uint32_t a0 = *(uint32_t*)&h2;
            f = *(const float2*)&Xst[(rb + g + 8) * 68 + kk];
            h2 = __float22half2_rn(f); uint32_t a1 = *(uint32_t*)&h2;
            f = *(const float2*)&Xst[(rb + g) * 68 + kk + 8];
            h2 = __float22half2_rn(f); uint32_t a2 = *(uint32_t*)&h2;
            f = *(const float2*)&Xst[(rb + g + 8) * 68 + kk + 8];
            h2 = __float22half2_rn(f); uint32_t a3 = *(uint32_t*)&h2;

            int kg = c * 64 + kk;
#pragma unroll
            for (int nt = 0; nt < 8; ++nt) {
                int n = nt * 8 + g;
                uint32_t b0 = *(const uint32_t*)&Wt[n * 520 + kg];
                uint32_t b1 = *(const uint32_t*)&Wt[n * 520 + kg + 8];
                mma16816(acc[nt], a0, a1, a2, a3, b0, b1);
            }
        }
    }

    const int rlo = row0 + rb + g;
    const int rhi = rlo + 8;
#pragma unroll
    for (int nt = 0; nt < 8; ++nt) {
        int c0 = nt * 8 + 2 * t;
        *(float2*)&d_h[(size_t)rlo * OUT_F + c0] = make_float2(acc[nt][0], acc[nt][1]);
        *(float2*)&d_h[(size_t)rhi * OUT_F + c0] = make_float2(acc[nt][2], acc[nt][3]);
    }
}

// ---------------------------------------------------------------------------
// K2: r_j = h[j] . a_right ; per-block max -> d_pmax
// ---------------------------------------------------------------------------
__global__ void k2_scores(const float* __restrict__ avec) {
    __shared__ float ar[64];
    __shared__ float red[256];
    const int tid = threadIdx.x;
    const int j   = blockIdx.x * 256 + tid;
    if (tid < 64) ar[tid] = avec[OUT_F + tid];   // a_right
    __syncthreads();

    const float4* h4 = (const float4*)&d_h[(size_t)j * OUT_F];
    float s = 0.f;
#pragma unroll
    for (int q = 0; q < 16; ++q) {
        float4 v = h4[q];
        s += v.x * ar[q * 4 + 0] + v.y * ar[q * 4 + 1]
           + v.z * ar[q * 4 + 2] + v.w * ar[q * 4 + 3];
    }
    d_r[j] = s;

    red[tid] = s;
    __syncthreads();
    for (int st = 128; st > 0; st >>= 1) {
        if (tid < st) red[tid] = fmaxf(red[tid], red[tid + st]);
        __syncthreads();
    }
    if (tid == 0) d_pmax[blockIdx.x] = red[0];
}

// ---------------------------------------------------------------------------
// K3: w_j = exp(r_j - m); build HpT[c][j] (fp16, n-major, padded to 80)
// ---------------------------------------------------------------------------
__global__ void k3_build() {
    __shared__ float hs[128][65];
    __shared__ float smax;
    const int tid = threadIdx.x;
    const int j0  = blockIdx.x * 128;
    if (tid == 0) {
        float m = d_pmax[0];
#pragma unroll
        for (int i = 1; i < 32; ++i) m = fmaxf(m, d_pmax[i]);
        smax = m;
    }
#pragma unroll
    for (int it = 0; it < 64; ++it) {
        int idx = it * 128 + tid;
        int rr = idx >> 6, cc = idx & 63;
        hs[rr][cc] = d_h[(size_t)(j0 + rr) * OUT_F + cc];
    }
    __syncthreads();
    float w = expf(d_r[j0 + tid] - smax);
#pragma unroll
    for (int c = 0; c < 80; ++c) {
        float v = (c < 64) ? w * hs[tid][c] : ((c == 64) ? w : 0.f);
        d_HpT[(size_t)c * N_NODES + j0 + tid] = __float2half(v);
    }
}

// ---------------------------------------------------------------------------
// K4: C[8192 x 80] = A(0/1 int32) @ Hp(fp16), then out = elu(num/den)
// 128 CTAs x 256 threads (8 warps = rg 0..3 x ng 0..1).
// A: raw int32 via 4-stage cp.async -> smem convert pass -> fp16 double buffer.
// B: 4-stage cp.async fp16. Fragments via ldmatrix (conflict-free, stride 72).
// One __syncthreads per chunk; conversion of chunk c+1 overlaps MMA of chunk c.
// ---------------------------------------------------------------------------
#define AI_STAGE (64 * 68)                 // ints per stage
#define AF_STAGE (64 * 72)                 // halves per stage
#define B_STAGE  (80 * 72)                 // halves per stage
#define OFF_AF   (4 * AI_STAGE * 4)                    // 69632
#define OFF_B    (OFF_AF + 2 * AF_STAGE * 2)           // 88064
#define OFF_DEN  (OFF_B + 4 * B_STAGE * 2)             // 134144
#define K4_SMEM  (OFF_DEN + 256)

__global__ void __launch_bounds__(256)
k4_main(const int* __restrict__ adj, float* __restrict__ out) {
    extern __shared__ char sm4[];
    int*    AIsm  = (int*)sm4;                          // [4][64][68] int32
    __half* Afp   = (__half*)(sm4 + OFF_AF);            // [2][64][72] fp16
    __half* Bsm   = (__half*)(sm4 + OFF_B);             // [4][80][72] fp16
    float*  den_s = (float*)(sm4 + OFF_DEN);

    const int tid  = threadIdx.x;
    const int warp = tid >> 5;
    const int lane = tid & 31;
    const int t    = lane & 3;
    const int rg   = warp >> 1;
    const int ng   = warp & 1;
    const int row0 = blockIdx.x * 64;

    const uint32_t A0 = (uint32_t)__cvta_generic_to_shared(Afp);
    const uint32_t B0 = (uint32_t)__cvta_generic_to_shared(Bsm);

    // ldmatrix lane addressing (verified in R3)
    const int quad = lane >> 3;            // 0..3
    const int qr   = lane & 7;
    const int rb   = rg * 16;
    const uint32_t aoff = (uint32_t)((rb + (quad & 1) * 8 + qr) * (72 * 2)
                                     + (quad >> 1) * 16);
    uint32_t boff[2];
#pragma unroll
    for (int p = 0; p < 2; ++p) {
        int n0 = (ng * 5 + 2 * p) * 8;
        boff[p] = (uint32_t)((n0 + (quad >> 1) * 8 + qr) * (72 * 2)
                             + (quad & 1) * 16);
    }
    const uint32_t boff4 = (uint32_t)(((ng * 5 + 4) * 8 + qr) * (72 * 2)
                                      + (quad & 1) * 16);

    // --- async producers: A int32 + B fp16 in one commit group per chunk ---
    auto issue = [&](int c) {
        int kc = c * 64;
        int*    Ad = AIsm + (c & 3) * AI_STAGE;
        __half* Bd = Bsm + (c & 3) * B_STAGE;
#pragma unroll
        for (int q = 0; q < 4; ++q) {
            int idx = q * 256 + tid;
            int rr = idx >> 4, c4 = idx & 15;
            cpa16(Ad + rr * 68 + c4 * 4,
                  adj + (size_t)(row0 + rr) * N_NODES + kc + c4 * 4);
        }
#pragma unroll
        for (int q = 0; q < 3; ++q) {
            int idx = q * 256 + tid;
            if (idx < 640) {
                int rr = idx >> 3, s = idx & 7;
                cpa16(Bd + rr * 72 + s * 8,
                      d_HpT + (size_t)rr * N_NODES + kc + s * 8);
            }
        }
    };

    // smem convert: int32 stage (c&3) -> fp16 buffer (c&1)
    auto convA = [&](int c) {
        const int4* src = (const int4*)(AIsm + (c & 3) * AI_STAGE);
        __half*     dst = Afp + (c & 1) * AF_STAGE;
#pragma unroll
        for (int q = 0; q < 4; ++q) {
            int idx = q * 256 + tid;
            int rr = idx >> 4, c4 = idx & 15;
            int4 v = src[rr * 17 + c4];
            uint32_t h01 = (v.x ? 0x3C00u : 0u) | (v.y ? 0x3C000000u : 0u);
            uint32_t h23 = (v.z ? 0x3C00u : 0u) | (v.w ? 0x3C000000u : 0u);
            *(uint2*)&dst[rr * 72 + c4 * 4] = make_uint2(h01, h23);
        }
    };

    issue(0); CP_COMMIT();
    issue(1); CP_COMMIT();
    issue(2); CP_COMMIT();

    float acc[5][4];
#pragma unroll
    for (int n = 0; n < 5; ++n)
#pragma unroll
        for (int i = 0; i < 4; ++i) acc[n][i] = 0.f;

    // prologue: land chunk 0, convert it
    CP_WAIT(2);
    __syncthreads();
    convA(0);
    __syncthreads();

    for (int c = 0; c < 128; ++c) {
        // keep the group count invariant: always commit (possibly empty)
        if (c + 3 < 128) issue(c + 3);
        CP_COMMIT();
        CP_WAIT(2);                       // group c+1 has landed

        if (c + 1 < 128) convA(c + 1);    // overlaps with MMA below (other warps)

        const uint32_t Ab = A0 + (c & 1) * (AF_STAGE * 2) + aoff;
        const uint32_t Bb = B0 + (c & 3) * (B_STAGE * 2);

#pragma unroll
        for (int ks = 0; ks < 4; ++ks) {
            uint32_t a0, a1, a2, a3;
            ldsm_x4(a0, a1, a2, a3, Ab + ks * 32);
            uint32_t b[10];
            ldsm_x4(b[0], b[1], b[2], b[3], Bb + boff[0] + ks * 32);
            ldsm_x4(b[4], b[5], b[6], b[7], Bb + boff[1] + ks * 32);
            ldsm_x2(b[8], b[9], Bb + boff4 + ks * 32);
#pragma unroll
            for (int nt = 0; nt < 5; ++nt)
                mma16816(acc[nt], a0, a1, a2, a3, b[2 * nt], b[2 * nt + 1]);
        }

        // make conv(c+1) visible; also fences Bsm stage reuse next iteration
        __syncthreads();
    }

    // epilogue: den is column 64 = global n-tile 8 = (ng=1, nt=3), t==0
    const int g   = lane >> 2;
    const int r0l = rb + g;
    if (ng == 1 && t == 0) {
        den_s[r0l]     = acc[3][0];
        den_s[r0l + 8] = acc[3][2];
    }
    __syncthreads();
    float inv_lo = 1.f / den_s[r0l];
    float inv_hi = 1.f / den_s[r0l + 8];

    const int rlo = row0 + r0l;
    const int rhi = rlo + 8;
#pragma unroll
    for (int nt = 0; nt < 5; ++nt) {
        int gt = ng * 5 + nt;
        if (gt >= 8) break;                 // tiles 8,9 are den/padding
        int c0 = gt * 8 + 2 * t;
        float2 vlo = make_float2(elu1(acc[nt][0] * inv_lo), elu1(acc[nt][1] * inv_lo));
        float2 vhi = make_float2(elu1(acc[nt][2] * inv_hi), elu1(acc[nt][3] * inv_hi));
        *(float2*)&out[(size_t)rlo * OUT_F + c0] = vlo;
        *(float2*)&out[(size_t)rhi * OUT_F + c0] = vhi;
    }
}

// ---------------------------------------------------------------------------
extern "C" void kernel_launch(void* const* d_in, const int* in_sizes, int n_in,
                              void* d_out, int out_size) {
    const float* X    = (const float*)d_in[0];   // node_features 8192x512
    const int*   adj  = (const int*)  d_in[1];   // adjacency 8192x8192
    const float* W    = (const float*)d_in[2];   // weight 512x64
    const float* avec = (const float*)d_in[3];   // attention vector 128x1
    float* out = (float*)d_out;                  // 8192x64

    cudaFuncSetAttribute(k1_mma, cudaFuncAttributeMaxDynamicSharedMemorySize, K1_SMEM);
    cudaFuncSetAttribute(k4_main, cudaFuncAttributeMaxDynamicSharedMemorySize, K4_SMEM);

    k1_mma<<<128, 128, K1_SMEM>>>(X, W);
    k2_scores<<<32, 256>>>(avec);
    k3_build<<<64, 128>>>();
    k4_main<<<128, 256, K4_SMEM>>>(adj, out);
}